// round 1
// baseline (speedup 1.0000x reference)
#include <cuda_runtime.h>

// PhysicsAttention fused kernel (fp32 scalar baseline, round 0)
// N=64, C=128, T=256, V=25, O=128, grid = N*T blocks, 128 threads/block.

#define NN 64
#define CC 128
#define TT 256
#define VV 25
#define OO 128

// dynamic smem layout (floats):
//   [0, 3584)              x_s   [128][28]   (row stride 28 for float4 align)
//   [0, 700)   (overlay)   sc    [25][28]    (scores/attn, used after x_s dead)
//   [3584, 6884)           q_s   [25][132]
//   [6884, 10184)          k_s   [25][132]
//   [10184, 13484)         v_s   [25][132]
#define XS_STRIDE 28
#define QS_STRIDE 132
#define SC_STRIDE 28
#define SMEM_FLOATS (3584 + 3 * 3300)
#define SMEM_BYTES (SMEM_FLOATS * 4)

__device__ __forceinline__ void project25(
    const float* __restrict__ x_s,   // [128][28]
    const float* __restrict__ W,     // [128][128] row-major (o, c)
    const float* __restrict__ B,     // [128]
    float* __restrict__ dst,         // [25][132]
    int o)
{
    float acc[VV];
    const float b = B[o];
#pragma unroll
    for (int v = 0; v < VV; ++v) acc[v] = b;

    const float4* wrow = reinterpret_cast<const float4*>(W + o * CC);
    for (int c4 = 0; c4 < CC / 4; ++c4) {
        float4 w4 = wrow[c4];
#pragma unroll
        for (int j = 0; j < 4; ++j) {
            float wval = (j == 0) ? w4.x : (j == 1) ? w4.y : (j == 2) ? w4.z : w4.w;
            const float* xr = x_s + (c4 * 4 + j) * XS_STRIDE;
#pragma unroll
            for (int g = 0; g < 6; ++g) {
                float4 a = *reinterpret_cast<const float4*>(xr + g * 4);
                acc[g * 4 + 0] = fmaf(a.x, wval, acc[g * 4 + 0]);
                acc[g * 4 + 1] = fmaf(a.y, wval, acc[g * 4 + 1]);
                acc[g * 4 + 2] = fmaf(a.z, wval, acc[g * 4 + 2]);
                acc[g * 4 + 3] = fmaf(a.w, wval, acc[g * 4 + 3]);
            }
            acc[24] = fmaf(xr[24], wval, acc[24]);
        }
    }
#pragma unroll
    for (int v = 0; v < VV; ++v) dst[v * QS_STRIDE + o] = acc[v];
}

__global__ void __launch_bounds__(128) phys_attn_kernel(
    const float* __restrict__ x,
    const float* __restrict__ wq, const float* __restrict__ bq,
    const float* __restrict__ wk, const float* __restrict__ bk,
    const float* __restrict__ wv, const float* __restrict__ bv,
    const float* __restrict__ bias_emb,
    const int*   __restrict__ hop,
    float* __restrict__ out)
{
    extern __shared__ float smem[];
    float* x_s = smem;              // [128][28]
    float* q_s = smem + 3584;       // [25][132]
    float* k_s = q_s + 3300;
    float* v_s = k_s + 3300;
    float* sc  = smem;              // [25][28] overlay (valid after projections)

    const int tid = threadIdx.x;
    const int blk = blockIdx.x;     // n*T + t
    const int n = blk / TT;
    const int t = blk - n * TT;

    // ---- Phase 1: stage x[n, :, t, :] into smem ----
    // x flat index: ((n*CC + c)*TT + t)*VV + v
    const float* xb = x + ((size_t)n * CC * TT + t) * VV;
    for (int i = tid; i < CC * VV; i += 128) {
        int c = i / VV;
        int v = i - c * VV;
        x_s[c * XS_STRIDE + v] = xb[(size_t)c * (TT * VV) + v];
    }
    __syncthreads();

    // ---- Phase 2: QKV projections (thread o owns column o) ----
    const int o = tid;
    project25(x_s, wq, bq, q_s, o);
    project25(x_s, wk, bk, k_s, o);
    project25(x_s, wv, bv, v_s, o);
    __syncthreads();   // x_s dead after this point; sc overlays it

    // ---- Phase 3: scores[v][w] = q[v].k[w]/sqrt(128) + bias ----
    const float scale = 0.08838834764831845f;  // 1/sqrt(128)
    for (int p = tid; p < VV * VV; p += 128) {
        int v = p / VV;
        int w = p - v * VV;
        const float4* qr = reinterpret_cast<const float4*>(q_s + v * QS_STRIDE);
        const float4* kr = reinterpret_cast<const float4*>(k_s + w * QS_STRIDE);
        float s0 = 0.f, s1 = 0.f, s2 = 0.f, s3 = 0.f;
#pragma unroll
        for (int j = 0; j < 32; ++j) {
            float4 a = qr[j];
            float4 b = kr[j];
            s0 = fmaf(a.x, b.x, s0);
            s1 = fmaf(a.y, b.y, s1);
            s2 = fmaf(a.z, b.z, s2);
            s3 = fmaf(a.w, b.w, s3);
        }
        float s = (s0 + s1) + (s2 + s3);
        sc[v * SC_STRIDE + w] = fmaf(s, scale, bias_emb[hop[p]]);
    }
    __syncthreads();

    // ---- Phase 4: softmax along w (25 rows, one thread per row) ----
    if (tid < VV) {
        float* row = sc + tid * SC_STRIDE;
        float mx = row[0];
#pragma unroll
        for (int w = 1; w < VV; ++w) mx = fmaxf(mx, row[w]);
        float sum = 0.f;
#pragma unroll
        for (int w = 0; w < VV; ++w) {
            float e = __expf(row[w] - mx);
            row[w] = e;
            sum += e;
        }
        float inv = 1.f / sum;
#pragma unroll
        for (int w = 0; w < VV; ++w) row[w] *= inv;
    }
    __syncthreads();

    // ---- Phase 5: out[v][o] = sum_w attn[v][w] * V[w][o] ----
    float vcol[VV];
#pragma unroll
    for (int w = 0; w < VV; ++w) vcol[w] = v_s[w * QS_STRIDE + o];

    // out flat index: ((n*OO + o)*TT + t)*VV + v
    float* ob = out + ((size_t)(n * OO + o) * TT + t) * VV;
#pragma unroll
    for (int v = 0; v < VV; ++v) {
        const float* row = sc + v * SC_STRIDE;
        float r = 0.f;
#pragma unroll
        for (int g = 0; g < 6; ++g) {
            float4 a = *reinterpret_cast<const float4*>(row + g * 4);
            r = fmaf(a.x, vcol[g * 4 + 0], r);
            r = fmaf(a.y, vcol[g * 4 + 1], r);
            r = fmaf(a.z, vcol[g * 4 + 2], r);
            r = fmaf(a.w, vcol[g * 4 + 3], r);
        }
        r = fmaf(row[24], vcol[24], r);
        ob[v] = r;
    }
}

extern "C" void kernel_launch(void* const* d_in, const int* in_sizes, int n_in,
                              void* d_out, int out_size)
{
    const float* x   = (const float*)d_in[0];
    const float* wq  = (const float*)d_in[1];
    const float* bq  = (const float*)d_in[2];
    const float* wk  = (const float*)d_in[3];
    const float* bk  = (const float*)d_in[4];
    const float* wv  = (const float*)d_in[5];
    const float* bv  = (const float*)d_in[6];
    const float* be  = (const float*)d_in[7];
    const int*   hop = (const int*)d_in[8];
    float* out = (float*)d_out;

    // idempotent, host-side only — safe under graph capture
    cudaFuncSetAttribute(phys_attn_kernel,
                         cudaFuncAttributeMaxDynamicSharedMemorySize, SMEM_BYTES);

    phys_attn_kernel<<<NN * TT, 128, SMEM_BYTES>>>(
        x, wq, bq, wk, bk, wv, bv, be, hop, out);
}

// round 2
// speedup vs baseline: 1.9077x; 1.9077x over previous
#include <cuda_runtime.h>

// PhysicsAttention round 1: L1-wavefront fixes + f32x2 packed FMA.
// N=64, C=128, T=256, V=25, O=128. grid = N*T blocks, 128 threads.

#define NN 64
#define CC 128
#define TT 256
#define VV 25
#define OO 128

// transposed weights scratch: [3][c][o]
__device__ float g_wt[3 * CC * OO];

// packed f32x2 helpers
#define FMA2(d, a, b) \
    asm("fma.rn.f32x2 %0, %1, %2, %3;" : "=l"(d) : "l"(a), "l"(b), "l"(d))
#define PACK2(d, s) \
    asm("mov.b64 %0, {%1, %1};" : "=l"(d) : "r"(__float_as_uint(s)))
#define UNPACK2(lo, hi, d) \
    asm("mov.b64 {%0, %1}, %2;" : "=f"(lo), "=f"(hi) : "l"(d))

typedef unsigned long long u64;

__global__ void __launch_bounds__(256) transpose_w_kernel(
    const float* __restrict__ wq, const float* __restrict__ wk,
    const float* __restrict__ wv)
{
    int i = blockIdx.x * blockDim.x + threadIdx.x;   // o*128 + c
    if (i < CC * OO) {
        int o = i >> 7, c = i & 127;
        g_wt[c * OO + o]               = wq[i];
        g_wt[CC * OO + c * OO + o]     = wk[i];
        g_wt[2 * CC * OO + c * OO + o] = wv[i];
    }
}

// smem layout (floats):
//   x_s  [128][28]  (3584)  -- overlaid by sc [25][28] (700) after phase 2
//   q_s  [25][132]  (3300)  -- overlaid by out_s after phase 3
//   k_s  [25][132]  (3300)
//   v_s  [25][132]  (3300)
#define XS 28
#define QS 132
#define SCS 28
#define SMEM_FLOATS (3584 + 3 * 3300)
#define SMEM_BYTES (SMEM_FLOATS * 4)

__global__ void __launch_bounds__(128) phys_attn_kernel(
    const float* __restrict__ x,
    const float* __restrict__ bq, const float* __restrict__ bk,
    const float* __restrict__ bv,
    const float* __restrict__ bias_emb,
    const int*   __restrict__ hop,
    float* __restrict__ out)
{
    extern __shared__ float smem[];
    float* x_s = smem;              // [128][28]
    float* q_s = smem + 3584;       // [25][132]
    float* k_s = q_s + 3300;
    float* v_s = k_s + 3300;
    float* sc  = smem;              // [25][28] overlay
    float* out_s = q_s;             // overlay after phase 3

    const int tid = threadIdx.x;
    const int blk = blockIdx.x;
    const int n = blk / TT;
    const int t = blk - n * TT;
    const int o = tid;

    // ---- Phase 1: stage x[n, :, t, :] (coalesced-ish 100B runs) ----
    const float* xb = x + ((size_t)n * CC * TT + t) * VV;
    for (int i = tid; i < CC * VV; i += 128) {
        int c = i / VV;
        int v = i - c * VV;
        x_s[c * XS + v] = __ldg(xb + (size_t)c * (TT * VV) + v);
    }
    __syncthreads();

    // ---- Phase 2: fused QKV projection, thread o owns column o ----
    {
        u64 aq[12], ak[12], av[12];
        float aq24, ak24, av24;
        {
            float b0 = __ldg(bq + o), b1 = __ldg(bk + o), b2 = __ldg(bv + o);
            u64 p0, p1, p2;
            PACK2(p0, b0); PACK2(p1, b1); PACK2(p2, b2);
#pragma unroll
            for (int j = 0; j < 12; ++j) { aq[j] = p0; ak[j] = p1; av[j] = p2; }
            aq24 = b0; ak24 = b1; av24 = b2;
        }
        const float* wtq = g_wt + o;
        const float* wtk = g_wt + CC * OO + o;
        const float* wtv = g_wt + 2 * CC * OO + o;

#pragma unroll 4
        for (int c = 0; c < CC; ++c) {
            float wq1 = __ldg(wtq + c * OO);
            float wk1 = __ldg(wtk + c * OO);
            float wv1 = __ldg(wtv + c * OO);
            u64 wq2, wk2, wv2;
            PACK2(wq2, wq1); PACK2(wk2, wk1); PACK2(wv2, wv1);

            const ulonglong2* xr = reinterpret_cast<const ulonglong2*>(x_s + c * XS);
#pragma unroll
            for (int g = 0; g < 6; ++g) {
                ulonglong2 xp = xr[g];               // 4 x values (2 pairs)
                FMA2(aq[2 * g],     xp.x, wq2);
                FMA2(aq[2 * g + 1], xp.y, wq2);
                FMA2(ak[2 * g],     xp.x, wk2);
                FMA2(ak[2 * g + 1], xp.y, wk2);
                FMA2(av[2 * g],     xp.x, wv2);
                FMA2(av[2 * g + 1], xp.y, wv2);
            }
            float x24 = x_s[c * XS + 24];
            aq24 = fmaf(x24, wq1, aq24);
            ak24 = fmaf(x24, wk1, ak24);
            av24 = fmaf(x24, wv1, av24);
        }
        // scatter to smem [v][o]
#pragma unroll
        for (int j = 0; j < 12; ++j) {
            float lo, hi;
            UNPACK2(lo, hi, aq[j]);
            q_s[(2 * j) * QS + o] = lo; q_s[(2 * j + 1) * QS + o] = hi;
            UNPACK2(lo, hi, ak[j]);
            k_s[(2 * j) * QS + o] = lo; k_s[(2 * j + 1) * QS + o] = hi;
            UNPACK2(lo, hi, av[j]);
            v_s[(2 * j) * QS + o] = lo; v_s[(2 * j + 1) * QS + o] = hi;
        }
        q_s[24 * QS + o] = aq24;
        k_s[24 * QS + o] = ak24;
        v_s[24 * QS + o] = av24;
    }
    __syncthreads();

    // ---- Phase 3: scores[v][w] = q[v].k[w]/sqrt(O) + bias ----
    const float scale = 0.08838834764831845f;   // 1/sqrt(128)
    float myscore[5];
    int myp[5];
#pragma unroll
    for (int r = 0; r < 5; ++r) {
        int p = tid + r * 128;
        myp[r] = p;
        if (p < VV * VV) {
            int v = p / VV;
            int w = p - v * VV;
            const ulonglong2* qr = reinterpret_cast<const ulonglong2*>(q_s + v * QS);
            const ulonglong2* kr = reinterpret_cast<const ulonglong2*>(k_s + w * QS);
            u64 a0 = 0, a1 = 0, a2 = 0, a3 = 0;
#pragma unroll
            for (int g = 0; g < 32; g += 2) {
                ulonglong2 qv = qr[g], kv = kr[g];
                FMA2(a0, qv.x, kv.x);
                FMA2(a1, qv.y, kv.y);
                ulonglong2 qv2 = qr[g + 1], kv2 = kr[g + 1];
                FMA2(a2, qv2.x, kv2.x);
                FMA2(a3, qv2.y, kv2.y);
            }
            float l0, h0, l1, h1, l2, h2, l3, h3;
            UNPACK2(l0, h0, a0); UNPACK2(l1, h1, a1);
            UNPACK2(l2, h2, a2); UNPACK2(l3, h3, a3);
            float s = ((l0 + h0) + (l1 + h1)) + ((l2 + h2) + (l3 + h3));
            myscore[r] = fmaf(s, scale, __ldg(bias_emb + __ldg(hop + p)));
        }
    }
    __syncthreads();   // x_s fully dead; sc region now writable
#pragma unroll
    for (int r = 0; r < 5; ++r) {
        int p = myp[r];
        if (p < VV * VV) {
            int v = p / VV;
            int w = p - v * VV;
            sc[v * SCS + w] = myscore[r];
        }
    }
    __syncthreads();

    // ---- Phase 4: softmax over w (one thread per row) ----
    if (tid < VV) {
        float* row = sc + tid * SCS;
        float mx = row[0];
#pragma unroll
        for (int w = 1; w < VV; ++w) mx = fmaxf(mx, row[w]);
        float sum = 0.f;
#pragma unroll
        for (int w = 0; w < VV; ++w) {
            float e = __expf(row[w] - mx);
            row[w] = e;
            sum += e;
        }
        float inv = 1.f / sum;
#pragma unroll
        for (int w = 0; w < VV; ++w) row[w] *= inv;
    }
    __syncthreads();

    // ---- Phase 5: out[v][o] = sum_w attn[v][w] * V[w][o] ----
    {
        u64 vc[12];
        float vc24;
#pragma unroll
        for (int j = 0; j < 12; ++j) {
            float lo = v_s[(2 * j) * QS + o];
            float hi = v_s[(2 * j + 1) * QS + o];
            asm("mov.b64 %0, {%1, %2};" : "=l"(vc[j])
                : "r"(__float_as_uint(lo)), "r"(__float_as_uint(hi)));
        }
        vc24 = v_s[24 * QS + o];

        float r[VV];
#pragma unroll
        for (int v = 0; v < VV; ++v) {
            const ulonglong2* ar = reinterpret_cast<const ulonglong2*>(sc + v * SCS);
            u64 acc = 0;
#pragma unroll
            for (int g = 0; g < 6; ++g) {
                ulonglong2 ap = ar[g];
                FMA2(acc, ap.x, vc[2 * g]);
                FMA2(acc, ap.y, vc[2 * g + 1]);
            }
            float lo, hi;
            UNPACK2(lo, hi, acc);
            r[v] = (lo + hi) + sc[v * SCS + 24] * vc24;
        }
        __syncthreads();   // q_s (out_s) reads from phase 3 are long done
#pragma unroll
        for (int v = 0; v < VV; ++v) out_s[v * QS + o] = r[v];
    }
    __syncthreads();

    // ---- Phase 6: coalesced store via smem bounce ----
    // out flat: ((n*OO + o)*TT + t)*VV + v  => base + o*TT*VV + v
    float* ob = out + ((size_t)n * OO * TT + t) * VV;
    for (int i = tid; i < OO * VV; i += 128) {
        int oo = i / VV;
        int v = i - oo * VV;
        ob[(size_t)oo * (TT * VV) + v] = out_s[v * QS + oo];
    }
}

extern "C" void kernel_launch(void* const* d_in, const int* in_sizes, int n_in,
                              void* d_out, int out_size)
{
    const float* x   = (const float*)d_in[0];
    const float* wq  = (const float*)d_in[1];
    const float* bq  = (const float*)d_in[2];
    const float* wk  = (const float*)d_in[3];
    const float* bk  = (const float*)d_in[4];
    const float* wv  = (const float*)d_in[5];
    const float* bv  = (const float*)d_in[6];
    const float* be  = (const float*)d_in[7];
    const int*   hop = (const int*)d_in[8];
    float* out = (float*)d_out;

    cudaFuncSetAttribute(phys_attn_kernel,
                         cudaFuncAttributeMaxDynamicSharedMemorySize, SMEM_BYTES);

    transpose_w_kernel<<<(CC * OO + 255) / 256, 256>>>(wq, wk, wv);
    phys_attn_kernel<<<NN * TT, 128, SMEM_BYTES>>>(
        x, bq, bk, bv, be, hop, out);
}

// round 3
// speedup vs baseline: 1.9082x; 1.0002x over previous
#include <cuda_runtime.h>

// PhysicsAttention round 1: L1-wavefront fixes + f32x2 packed FMA.
// N=64, C=128, T=256, V=25, O=128. grid = N*T blocks, 128 threads.

#define NN 64
#define CC 128
#define TT 256
#define VV 25
#define OO 128

// transposed weights scratch: [3][c][o]
__device__ float g_wt[3 * CC * OO];

// packed f32x2 helpers
#define FMA2(d, a, b) \
    asm("fma.rn.f32x2 %0, %1, %2, %3;" : "=l"(d) : "l"(a), "l"(b), "l"(d))
#define PACK2(d, s) \
    asm("mov.b64 %0, {%1, %1};" : "=l"(d) : "r"(__float_as_uint(s)))
#define UNPACK2(lo, hi, d) \
    asm("mov.b64 {%0, %1}, %2;" : "=f"(lo), "=f"(hi) : "l"(d))

typedef unsigned long long u64;

__global__ void __launch_bounds__(256) transpose_w_kernel(
    const float* __restrict__ wq, const float* __restrict__ wk,
    const float* __restrict__ wv)
{
    int i = blockIdx.x * blockDim.x + threadIdx.x;   // o*128 + c
    if (i < CC * OO) {
        int o = i >> 7, c = i & 127;
        g_wt[c * OO + o]               = wq[i];
        g_wt[CC * OO + c * OO + o]     = wk[i];
        g_wt[2 * CC * OO + c * OO + o] = wv[i];
    }
}

// smem layout (floats):
//   x_s  [128][28]  (3584)  -- overlaid by sc [25][28] (700) after phase 2
//   q_s  [25][132]  (3300)  -- overlaid by out_s after phase 3
//   k_s  [25][132]  (3300)
//   v_s  [25][132]  (3300)
#define XS 28
#define QS 132
#define SCS 28
#define SMEM_FLOATS (3584 + 3 * 3300)
#define SMEM_BYTES (SMEM_FLOATS * 4)

__global__ void __launch_bounds__(128) phys_attn_kernel(
    const float* __restrict__ x,
    const float* __restrict__ bq, const float* __restrict__ bk,
    const float* __restrict__ bv,
    const float* __restrict__ bias_emb,
    const int*   __restrict__ hop,
    float* __restrict__ out)
{
    extern __shared__ float smem[];
    float* x_s = smem;              // [128][28]
    float* q_s = smem + 3584;       // [25][132]
    float* k_s = q_s + 3300;
    float* v_s = k_s + 3300;
    float* sc  = smem;              // [25][28] overlay
    float* out_s = q_s;             // overlay after phase 3

    const int tid = threadIdx.x;
    const int blk = blockIdx.x;
    const int n = blk / TT;
    const int t = blk - n * TT;
    const int o = tid;

    // ---- Phase 1: stage x[n, :, t, :] (coalesced-ish 100B runs) ----
    const float* xb = x + ((size_t)n * CC * TT + t) * VV;
    for (int i = tid; i < CC * VV; i += 128) {
        int c = i / VV;
        int v = i - c * VV;
        x_s[c * XS + v] = __ldg(xb + (size_t)c * (TT * VV) + v);
    }
    __syncthreads();

    // ---- Phase 2: fused QKV projection, thread o owns column o ----
    {
        u64 aq[12], ak[12], av[12];
        float aq24, ak24, av24;
        {
            float b0 = __ldg(bq + o), b1 = __ldg(bk + o), b2 = __ldg(bv + o);
            u64 p0, p1, p2;
            PACK2(p0, b0); PACK2(p1, b1); PACK2(p2, b2);
#pragma unroll
            for (int j = 0; j < 12; ++j) { aq[j] = p0; ak[j] = p1; av[j] = p2; }
            aq24 = b0; ak24 = b1; av24 = b2;
        }
        const float* wtq = g_wt + o;
        const float* wtk = g_wt + CC * OO + o;
        const float* wtv = g_wt + 2 * CC * OO + o;

#pragma unroll 4
        for (int c = 0; c < CC; ++c) {
            float wq1 = __ldg(wtq + c * OO);
            float wk1 = __ldg(wtk + c * OO);
            float wv1 = __ldg(wtv + c * OO);
            u64 wq2, wk2, wv2;
            PACK2(wq2, wq1); PACK2(wk2, wk1); PACK2(wv2, wv1);

            const ulonglong2* xr = reinterpret_cast<const ulonglong2*>(x_s + c * XS);
#pragma unroll
            for (int g = 0; g < 6; ++g) {
                ulonglong2 xp = xr[g];               // 4 x values (2 pairs)
                FMA2(aq[2 * g],     xp.x, wq2);
                FMA2(aq[2 * g + 1], xp.y, wq2);
                FMA2(ak[2 * g],     xp.x, wk2);
                FMA2(ak[2 * g + 1], xp.y, wk2);
                FMA2(av[2 * g],     xp.x, wv2);
                FMA2(av[2 * g + 1], xp.y, wv2);
            }
            float x24 = x_s[c * XS + 24];
            aq24 = fmaf(x24, wq1, aq24);
            ak24 = fmaf(x24, wk1, ak24);
            av24 = fmaf(x24, wv1, av24);
        }
        // scatter to smem [v][o]
#pragma unroll
        for (int j = 0; j < 12; ++j) {
            float lo, hi;
            UNPACK2(lo, hi, aq[j]);
            q_s[(2 * j) * QS + o] = lo; q_s[(2 * j + 1) * QS + o] = hi;
            UNPACK2(lo, hi, ak[j]);
            k_s[(2 * j) * QS + o] = lo; k_s[(2 * j + 1) * QS + o] = hi;
            UNPACK2(lo, hi, av[j]);
            v_s[(2 * j) * QS + o] = lo; v_s[(2 * j + 1) * QS + o] = hi;
        }
        q_s[24 * QS + o] = aq24;
        k_s[24 * QS + o] = ak24;
        v_s[24 * QS + o] = av24;
    }
    __syncthreads();

    // ---- Phase 3: scores[v][w] = q[v].k[w]/sqrt(O) + bias ----
    const float scale = 0.08838834764831845f;   // 1/sqrt(128)
    float myscore[5];
    int myp[5];
#pragma unroll
    for (int r = 0; r < 5; ++r) {
        int p = tid + r * 128;
        myp[r] = p;
        if (p < VV * VV) {
            int v = p / VV;
            int w = p - v * VV;
            const ulonglong2* qr = reinterpret_cast<const ulonglong2*>(q_s + v * QS);
            const ulonglong2* kr = reinterpret_cast<const ulonglong2*>(k_s + w * QS);
            u64 a0 = 0, a1 = 0, a2 = 0, a3 = 0;
#pragma unroll
            for (int g = 0; g < 32; g += 2) {
                ulonglong2 qv = qr[g], kv = kr[g];
                FMA2(a0, qv.x, kv.x);
                FMA2(a1, qv.y, kv.y);
                ulonglong2 qv2 = qr[g + 1], kv2 = kr[g + 1];
                FMA2(a2, qv2.x, kv2.x);
                FMA2(a3, qv2.y, kv2.y);
            }
            float l0, h0, l1, h1, l2, h2, l3, h3;
            UNPACK2(l0, h0, a0); UNPACK2(l1, h1, a1);
            UNPACK2(l2, h2, a2); UNPACK2(l3, h3, a3);
            float s = ((l0 + h0) + (l1 + h1)) + ((l2 + h2) + (l3 + h3));
            myscore[r] = fmaf(s, scale, __ldg(bias_emb + __ldg(hop + p)));
        }
    }
    __syncthreads();   // x_s fully dead; sc region now writable
#pragma unroll
    for (int r = 0; r < 5; ++r) {
        int p = myp[r];
        if (p < VV * VV) {
            int v = p / VV;
            int w = p - v * VV;
            sc[v * SCS + w] = myscore[r];
        }
    }
    __syncthreads();

    // ---- Phase 4: softmax over w (one thread per row) ----
    if (tid < VV) {
        float* row = sc + tid * SCS;
        float mx = row[0];
#pragma unroll
        for (int w = 1; w < VV; ++w) mx = fmaxf(mx, row[w]);
        float sum = 0.f;
#pragma unroll
        for (int w = 0; w < VV; ++w) {
            float e = __expf(row[w] - mx);
            row[w] = e;
            sum += e;
        }
        float inv = 1.f / sum;
#pragma unroll
        for (int w = 0; w < VV; ++w) row[w] *= inv;
    }
    __syncthreads();

    // ---- Phase 5: out[v][o] = sum_w attn[v][w] * V[w][o] ----
    {
        u64 vc[12];
        float vc24;
#pragma unroll
        for (int j = 0; j < 12; ++j) {
            float lo = v_s[(2 * j) * QS + o];
            float hi = v_s[(2 * j + 1) * QS + o];
            asm("mov.b64 %0, {%1, %2};" : "=l"(vc[j])
                : "r"(__float_as_uint(lo)), "r"(__float_as_uint(hi)));
        }
        vc24 = v_s[24 * QS + o];

        float r[VV];
#pragma unroll
        for (int v = 0; v < VV; ++v) {
            const ulonglong2* ar = reinterpret_cast<const ulonglong2*>(sc + v * SCS);
            u64 acc = 0;
#pragma unroll
            for (int g = 0; g < 6; ++g) {
                ulonglong2 ap = ar[g];
                FMA2(acc, ap.x, vc[2 * g]);
                FMA2(acc, ap.y, vc[2 * g + 1]);
            }
            float lo, hi;
            UNPACK2(lo, hi, acc);
            r[v] = (lo + hi) + sc[v * SCS + 24] * vc24;
        }
        __syncthreads();   // q_s (out_s) reads from phase 3 are long done
#pragma unroll
        for (int v = 0; v < VV; ++v) out_s[v * QS + o] = r[v];
    }
    __syncthreads();

    // ---- Phase 6: coalesced store via smem bounce ----
    // out flat: ((n*OO + o)*TT + t)*VV + v  => base + o*TT*VV + v
    float* ob = out + ((size_t)n * OO * TT + t) * VV;
    for (int i = tid; i < OO * VV; i += 128) {
        int oo = i / VV;
        int v = i - oo * VV;
        ob[(size_t)oo * (TT * VV) + v] = out_s[v * QS + oo];
    }
}

extern "C" void kernel_launch(void* const* d_in, const int* in_sizes, int n_in,
                              void* d_out, int out_size)
{
    const float* x   = (const float*)d_in[0];
    const float* wq  = (const float*)d_in[1];
    const float* bq  = (const float*)d_in[2];
    const float* wk  = (const float*)d_in[3];
    const float* bk  = (const float*)d_in[4];
    const float* wv  = (const float*)d_in[5];
    const float* bv  = (const float*)d_in[6];
    const float* be  = (const float*)d_in[7];
    const int*   hop = (const int*)d_in[8];
    float* out = (float*)d_out;

    cudaFuncSetAttribute(phys_attn_kernel,
                         cudaFuncAttributeMaxDynamicSharedMemorySize, SMEM_BYTES);

    transpose_w_kernel<<<(CC * OO + 255) / 256, 256>>>(wq, wk, wv);
    phys_attn_kernel<<<NN * TT, 128, SMEM_BYTES>>>(
        x, bq, bk, bv, be, hop, out);
}

// round 5
// speedup vs baseline: 3.9696x; 2.0803x over previous
#include <cuda_runtime.h>
#include <cuda_fp16.h>
#include <cstdint>

typedef unsigned int u32;

#define NN 64
#define CC 128
#define TT 256
#define VV 25
#define OO 128
#define TILES 52
#define THREADS 256
#define SCALE 0.08838834764831845f   // 1/sqrt(128)

#define HS 136                        // half-row stride (pad 8) -> conflict-free frags
// smem byte offsets
#define XH_OFF 0                      // x tile fp16 [128][HS]
#define WK_OFF 34816                  // Wk fp16, then K' (kh) overlay
#define WV_OFF 69632                  // Wv fp16, then V'^T (vT) overlay
#define WQ_OFF 104448                 // Wq fp16
#define BT_OFF 139264                 // bias table [25][25] f32
#define BQ_OFF 141764                 // bq f32 [128]
#define BK_OFF 142276
#define BV_OFF 142788
#define SMEM_BYTES 143360
// outs f32 [128][129] overlays [0, 66048) (xh + kh region, dead by then)

static __device__ __forceinline__ void mma16816(
    float* d, u32 a0, u32 a1, u32 a2, u32 a3, u32 b0, u32 b1)
{
    asm volatile(
        "mma.sync.aligned.m16n8k16.row.col.f32.f16.f16.f32 "
        "{%0,%1,%2,%3}, {%4,%5,%6,%7}, {%8,%9}, {%0,%1,%2,%3};"
        : "+f"(d[0]), "+f"(d[1]), "+f"(d[2]), "+f"(d[3])
        : "r"(a0), "r"(a1), "r"(a2), "r"(a3), "r"(b0), "r"(b1));
}
static __device__ __forceinline__ u32 h2u(__half2 h) {
    u32 r; asm("mov.b32 %0, %1;" : "=r"(r) : "r"(*(u32*)&h)); return r;
}

__global__ void __launch_bounds__(THREADS, 1) phys_attn_mma(
    const float* __restrict__ x,
    const float* __restrict__ wq, const float* __restrict__ bq,
    const float* __restrict__ wk, const float* __restrict__ bk,
    const float* __restrict__ wv, const float* __restrict__ bv,
    const float* __restrict__ bias_emb,
    const int*   __restrict__ hop,
    float* __restrict__ out)
{
    extern __shared__ char sm[];
    __half* xh = (__half*)(sm + XH_OFF);
    __half* kh = (__half*)(sm + WK_OFF);   // Wk, later K'
    __half* vh = (__half*)(sm + WV_OFF);   // Wv, later V'^T
    __half* qh = (__half*)(sm + WQ_OFF);   // Wq
    float* bias_s = (float*)(sm + BT_OFF);
    float* bqs = (float*)(sm + BQ_OFF);
    float* bks = (float*)(sm + BK_OFF);
    float* bvs = (float*)(sm + BV_OFF);
    float* outs = (float*)sm;              // [128][129] overlay

    const int tid = threadIdx.x;
    const int wid = tid >> 5, lid = tid & 31;
    const int gr = lid >> 2, q4 = lid & 3;
    const int m0 = wid * 16;

    const int n = blockIdx.x / TILES;
    const int tile = blockIdx.x - n * TILES;
    const int t0 = tile * 5;
    const int nvalid = (tile < 51) ? 125 : 25;

    // ---- stage weights fp32 -> fp16 (row stride HS halves) ----
    for (int i = tid; i < 4096; i += THREADS) {
        int o = i >> 5, c4 = (i & 31) << 2;
        float4 fq = __ldg((const float4*)(wq + o * CC + c4));
        float4 fk = __ldg((const float4*)(wk + o * CC + c4));
        float4 fv = __ldg((const float4*)(wv + o * CC + c4));
        *(__half2*)(qh + o * HS + c4)     = __floats2half2_rn(fq.x, fq.y);
        *(__half2*)(qh + o * HS + c4 + 2) = __floats2half2_rn(fq.z, fq.w);
        *(__half2*)(kh + o * HS + c4)     = __floats2half2_rn(fk.x, fk.y);
        *(__half2*)(kh + o * HS + c4 + 2) = __floats2half2_rn(fk.z, fk.w);
        *(__half2*)(vh + o * HS + c4)     = __floats2half2_rn(fv.x, fv.y);
        *(__half2*)(vh + o * HS + c4 + 2) = __floats2half2_rn(fv.z, fv.w);
    }
    // ---- stage x tile: xh[m][c], m=(dt*25+v), zero-pad m>=nvalid ----
    const float* xb = x + (size_t)n * CC * TT * VV + (size_t)t0 * VV;
    for (int i = tid; i < CC * 128; i += THREADS) {
        int c = i >> 7, m = i & 127;
        float val = (m < nvalid) ? __ldg(xb + (size_t)c * (TT * VV) + m) : 0.f;
        xh[m * HS + c] = __float2half_rn(val);
    }
    if (tid < OO) {
        bqs[tid] = __ldg(bq + tid);
        bks[tid] = __ldg(bk + tid);
        bvs[tid] = __ldg(bv + tid);
    }
    for (int i = tid; i < VV * VV; i += THREADS)
        bias_s[i] = __ldg(bias_emb + __ldg(hop + i));
    __syncthreads();

    // ---- preload A fragments of x (reused by all 3 projections) ----
    u32 af[8][4];
#pragma unroll
    for (int kt = 0; kt < 8; ++kt) {
        int base = kt * 16 + q4 * 2;
        af[kt][0] = *(const u32*)(xh + (m0 + gr) * HS + base);
        af[kt][1] = *(const u32*)(xh + (m0 + gr + 8) * HS + base);
        af[kt][2] = *(const u32*)(xh + (m0 + gr) * HS + base + 8);
        af[kt][3] = *(const u32*)(xh + (m0 + gr + 8) * HS + base + 8);
    }

    float d[16][4];

    // ---- K projection ----
#pragma unroll
    for (int j = 0; j < 16; ++j) { d[j][0] = d[j][1] = d[j][2] = d[j][3] = 0.f; }
#pragma unroll
    for (int kt = 0; kt < 8; ++kt) {
#pragma unroll
        for (int j = 0; j < 16; ++j) {
            const __half* bp = kh + (j * 8 + gr) * HS + kt * 16 + q4 * 2;
            mma16816(d[j], af[kt][0], af[kt][1], af[kt][2], af[kt][3],
                     *(const u32*)bp, *(const u32*)(bp + 8));
        }
    }
    __syncthreads();   // all warps done reading Wk
    // write K' (+bk) as fp16 into kh region
#pragma unroll
    for (int j = 0; j < 16; ++j) {
        int col = j * 8 + q4 * 2;
        float b0 = bks[col], b1 = bks[col + 1];
        *(__half2*)(kh + (m0 + gr) * HS + col) =
            __floats2half2_rn(d[j][0] + b0, d[j][1] + b1);
        *(__half2*)(kh + (m0 + gr + 8) * HS + col) =
            __floats2half2_rn(d[j][2] + b0, d[j][3] + b1);
    }

    // ---- V projection ----
#pragma unroll
    for (int j = 0; j < 16; ++j) { d[j][0] = d[j][1] = d[j][2] = d[j][3] = 0.f; }
#pragma unroll
    for (int kt = 0; kt < 8; ++kt) {
#pragma unroll
        for (int j = 0; j < 16; ++j) {
            const __half* bp = vh + (j * 8 + gr) * HS + kt * 16 + q4 * 2;
            mma16816(d[j], af[kt][0], af[kt][1], af[kt][2], af[kt][3],
                     *(const u32*)bp, *(const u32*)(bp + 8));
        }
    }
    __syncthreads();   // all warps done reading Wv; kh complete
    // write V'^T (+bv): vT[o][w]
#pragma unroll
    for (int j = 0; j < 16; ++j) {
        int col = j * 8 + q4 * 2;
        float b0 = bvs[col], b1 = bvs[col + 1];
        vh[col * HS + (m0 + gr)]           = __float2half_rn(d[j][0] + b0);
        vh[(col + 1) * HS + (m0 + gr)]     = __float2half_rn(d[j][1] + b1);
        vh[col * HS + (m0 + gr + 8)]       = __float2half_rn(d[j][2] + b0);
        vh[(col + 1) * HS + (m0 + gr + 8)] = __float2half_rn(d[j][3] + b1);
    }

    // ---- Q projection (kept in registers, packed fp16) ----
#pragma unroll
    for (int j = 0; j < 16; ++j) { d[j][0] = d[j][1] = d[j][2] = d[j][3] = 0.f; }
#pragma unroll
    for (int kt = 0; kt < 8; ++kt) {
#pragma unroll
        for (int j = 0; j < 16; ++j) {
            const __half* bp = qh + (j * 8 + gr) * HS + kt * 16 + q4 * 2;
            mma16816(d[j], af[kt][0], af[kt][1], af[kt][2], af[kt][3],
                     *(const u32*)bp, *(const u32*)(bp + 8));
        }
    }
    u32 qp0[16], qp1[16];
#pragma unroll
    for (int j = 0; j < 16; ++j) {
        int col = j * 8 + q4 * 2;
        float b0 = bqs[col], b1 = bqs[col + 1];
        qp0[j] = h2u(__floats2half2_rn(d[j][0] + b0, d[j][1] + b1));
        qp1[j] = h2u(__floats2half2_rn(d[j][2] + b0, d[j][3] + b1));
    }
    __syncthreads();   // kh, vT ready for all warps

    // ---- S = Q K'^T ----
#pragma unroll
    for (int j = 0; j < 16; ++j) { d[j][0] = d[j][1] = d[j][2] = d[j][3] = 0.f; }
#pragma unroll
    for (int kt = 0; kt < 8; ++kt) {
        u32 a0 = qp0[2 * kt], a1 = qp1[2 * kt];
        u32 a2 = qp0[2 * kt + 1], a3 = qp1[2 * kt + 1];
#pragma unroll
        for (int j = 0; j < 16; ++j) {
            const __half* bp = kh + (j * 8 + gr) * HS + kt * 16 + q4 * 2;
            mma16816(d[j], a0, a1, a2, a3,
                     *(const u32*)bp, *(const u32*)(bp + 8));
        }
    }
    __syncthreads();   // all S reads of kh done -> outs overlay becomes legal

    // ---- softmax (registers; rows mA=m0+gr, mB=mA+8; quad shfl reduce) ----
    const int mA = m0 + gr, mB = mA + 8;
    const bool actA = mA < nvalid, actB = mB < nvalid;
    const int tbA = mA / VV, vlA = mA - tbA * VV, loA = tbA * VV;
    const int tbB = mB / VV, vlB = mB - tbB * VV, loB = tbB * VV;
    float mxA = -1e30f, mxB = -1e30f;
#pragma unroll
    for (int j = 0; j < 16; ++j) {
        int w0 = j * 8 + q4 * 2;
        int rA = w0 - loA, rB = w0 - loB;
        if (actA && rA >= 0 && rA < VV) {
            d[j][0] = fmaf(d[j][0], SCALE, bias_s[vlA * VV + rA]);
            mxA = fmaxf(mxA, d[j][0]);
        }
        if (actA && rA + 1 >= 0 && rA + 1 < VV) {
            d[j][1] = fmaf(d[j][1], SCALE, bias_s[vlA * VV + rA + 1]);
            mxA = fmaxf(mxA, d[j][1]);
        }
        if (actB && rB >= 0 && rB < VV) {
            d[j][2] = fmaf(d[j][2], SCALE, bias_s[vlB * VV + rB]);
            mxB = fmaxf(mxB, d[j][2]);
        }
        if (actB && rB + 1 >= 0 && rB + 1 < VV) {
            d[j][3] = fmaf(d[j][3], SCALE, bias_s[vlB * VV + rB + 1]);
            mxB = fmaxf(mxB, d[j][3]);
        }
    }
    mxA = fmaxf(mxA, __shfl_xor_sync(0xffffffffu, mxA, 1));
    mxA = fmaxf(mxA, __shfl_xor_sync(0xffffffffu, mxA, 2));
    mxB = fmaxf(mxB, __shfl_xor_sync(0xffffffffu, mxB, 1));
    mxB = fmaxf(mxB, __shfl_xor_sync(0xffffffffu, mxB, 2));
    float smA = 0.f, smB = 0.f;
#pragma unroll
    for (int j = 0; j < 16; ++j) {
        int w0 = j * 8 + q4 * 2;
        int rA = w0 - loA, rB = w0 - loB;
        float e0 = 0.f, e1 = 0.f, e2 = 0.f, e3 = 0.f;
        if (actA && rA >= 0 && rA < VV)         e0 = __expf(d[j][0] - mxA);
        if (actA && rA + 1 >= 0 && rA + 1 < VV) e1 = __expf(d[j][1] - mxA);
        if (actB && rB >= 0 && rB < VV)         e2 = __expf(d[j][2] - mxB);
        if (actB && rB + 1 >= 0 && rB + 1 < VV) e3 = __expf(d[j][3] - mxB);
        d[j][0] = e0; d[j][1] = e1; d[j][2] = e2; d[j][3] = e3;
        smA += e0 + e1; smB += e2 + e3;
    }
    smA += __shfl_xor_sync(0xffffffffu, smA, 1);
    smA += __shfl_xor_sync(0xffffffffu, smA, 2);
    smB += __shfl_xor_sync(0xffffffffu, smB, 1);
    smB += __shfl_xor_sync(0xffffffffu, smB, 2);
    float ivA = actA ? (1.f / smA) : 0.f;
    float ivB = actB ? (1.f / smB) : 0.f;
    u32 pp0[16], pp1[16];
#pragma unroll
    for (int j = 0; j < 16; ++j) {
        pp0[j] = h2u(__floats2half2_rn(d[j][0] * ivA, d[j][1] * ivA));
        pp1[j] = h2u(__floats2half2_rn(d[j][2] * ivB, d[j][3] * ivB));
    }

    // ---- AV = P V' (B from vT[o][w]) ----
#pragma unroll
    for (int j = 0; j < 16; ++j) { d[j][0] = d[j][1] = d[j][2] = d[j][3] = 0.f; }
#pragma unroll
    for (int kt = 0; kt < 8; ++kt) {
        u32 a0 = pp0[2 * kt], a1 = pp1[2 * kt];
        u32 a2 = pp0[2 * kt + 1], a3 = pp1[2 * kt + 1];
#pragma unroll
        for (int j = 0; j < 16; ++j) {
            const __half* bp = vh + (j * 8 + gr) * HS + kt * 16 + q4 * 2;
            mma16816(d[j], a0, a1, a2, a3,
                     *(const u32*)bp, *(const u32*)(bp + 8));
        }
    }
    // ---- write outs[m][o] (overlay on xh/kh region) ----
#pragma unroll
    for (int j = 0; j < 16; ++j) {
        int col = j * 8 + q4 * 2;
        outs[mA * 129 + col] = d[j][0];
        outs[mA * 129 + col + 1] = d[j][1];
        outs[mB * 129 + col] = d[j][2];
        outs[mB * 129 + col + 1] = d[j][3];
    }
    __syncthreads();

    // ---- coalesced store: warp per o-row; 125 contiguous floats each ----
    float* ob = out + (size_t)n * OO * TT * VV + (size_t)t0 * VV;
    for (int orow = wid; orow < OO; orow += 8) {
        float* dst = ob + (size_t)orow * (TT * VV);
#pragma unroll
        for (int p = 0; p < 4; ++p) {
            int m = lid + p * 32;
            if (m < nvalid) dst[m] = outs[m * 129 + orow];
        }
    }
}

extern "C" void kernel_launch(void* const* d_in, const int* in_sizes, int n_in,
                              void* d_out, int out_size)
{
    const float* x   = (const float*)d_in[0];
    const float* wq  = (const float*)d_in[1];
    const float* bq  = (const float*)d_in[2];
    const float* wk  = (const float*)d_in[3];
    const float* bk  = (const float*)d_in[4];
    const float* wv  = (const float*)d_in[5];
    const float* bv  = (const float*)d_in[6];
    const float* be  = (const float*)d_in[7];
    const int*   hop = (const int*)d_in[8];
    float* out = (float*)d_out;

    cudaFuncSetAttribute(phys_attn_mma,
                         cudaFuncAttributeMaxDynamicSharedMemorySize, SMEM_BYTES);

    phys_attn_mma<<<NN * TILES, THREADS, SMEM_BYTES>>>(
        x, wq, bq, wk, bk, wv, bv, be, hop, out);
}

// round 6
// speedup vs baseline: 4.5702x; 1.1513x over previous
#include <cuda_runtime.h>
#include <cuda_fp16.h>
#include <cstdint>

typedef unsigned int u32;

#define NN 64
#define CC 128
#define TT 256
#define VV 25
#define OO 128
#define TILES 52
#define THREADS 512
#define SCALE 0.08838834764831845f   // 1/sqrt(128)

#define HS 136                        // half-row stride (pad 8): conflict-free frags
// smem byte offsets
#define XH_OFF 0                      // x tile fp16 [128][HS]; later outs overlay
#define WK_OFF 34816                  // Wk fp16 -> K' overlay; later outs tail
#define WV_OFF 69632                  // Wv fp16 -> V'^T overlay
#define WQ_OFF 104448                 // Wq fp16 -> Q' overlay -> ps overlay
#define BT_OFF 139264                 // bias table [25][25] f32
#define BQ_OFF 141764
#define BK_OFF 142276
#define BV_OFF 142788
#define SMEM_BYTES 143360

static __device__ __forceinline__ void mma16816(
    float* d, u32 a0, u32 a1, u32 a2, u32 a3, u32 b0, u32 b1)
{
    asm volatile(
        "mma.sync.aligned.m16n8k16.row.col.f32.f16.f16.f32 "
        "{%0,%1,%2,%3}, {%4,%5,%6,%7}, {%8,%9}, {%0,%1,%2,%3};"
        : "+f"(d[0]), "+f"(d[1]), "+f"(d[2]), "+f"(d[3])
        : "r"(a0), "r"(a1), "r"(a2), "r"(a3), "r"(b0), "r"(b1));
}
static __device__ __forceinline__ u32 h2u(__half2 h) {
    u32 r; asm("mov.b32 %0, %1;" : "=r"(r) : "r"(*(u32*)&h)); return r;
}

__global__ void __launch_bounds__(THREADS, 1) phys_attn_mma(
    const float* __restrict__ x,
    const float* __restrict__ wq, const float* __restrict__ bq,
    const float* __restrict__ wk, const float* __restrict__ bk,
    const float* __restrict__ wv, const float* __restrict__ bv,
    const float* __restrict__ bias_emb,
    const int*   __restrict__ hop,
    float* __restrict__ out)
{
    extern __shared__ char sm[];
    __half* xh = (__half*)(sm + XH_OFF);
    __half* kh = (__half*)(sm + WK_OFF);   // Wk -> K'
    __half* vh = (__half*)(sm + WV_OFF);   // Wv -> V'^T
    __half* qh = (__half*)(sm + WQ_OFF);   // Wq -> Q'
    float* bias_s = (float*)(sm + BT_OFF);
    float* bqs = (float*)(sm + BQ_OFF);
    float* bks = (float*)(sm + BK_OFF);
    float* bvs = (float*)(sm + BV_OFF);
    float* ps   = (float*)(sm + WQ_OFF);   // P [128][26] overlay (after S)
    float* outs = (float*)sm;              // [128][129] overlay (after S)

    const int tid = threadIdx.x;
    const int wid = tid >> 5, lid = tid & 31;
    const int gr = lid >> 2, q4 = lid & 3;
    const int ms = wid >> 1;               // m-strip 0..7
    const int half = wid & 1;
    const int m0 = ms * 16;
    const int co = half * 64;              // this warp's N-column base

    const int n = blockIdx.x / TILES;
    const int tile = blockIdx.x - n * TILES;
    const int t0 = tile * 5;
    const int nvalid = (tile < 51) ? 125 : 25;

    // ---- stage weights fp32 -> fp16 ----
    for (int i = tid; i < 4096; i += THREADS) {
        int o = i >> 5, c4 = (i & 31) << 2;
        float4 fq = __ldg((const float4*)(wq + o * CC + c4));
        float4 fk = __ldg((const float4*)(wk + o * CC + c4));
        float4 fv = __ldg((const float4*)(wv + o * CC + c4));
        *(__half2*)(qh + o * HS + c4)     = __floats2half2_rn(fq.x, fq.y);
        *(__half2*)(qh + o * HS + c4 + 2) = __floats2half2_rn(fq.z, fq.w);
        *(__half2*)(kh + o * HS + c4)     = __floats2half2_rn(fk.x, fk.y);
        *(__half2*)(kh + o * HS + c4 + 2) = __floats2half2_rn(fk.z, fk.w);
        *(__half2*)(vh + o * HS + c4)     = __floats2half2_rn(fv.x, fv.y);
        *(__half2*)(vh + o * HS + c4 + 2) = __floats2half2_rn(fv.z, fv.w);
    }
    // ---- stage x tile fp16: xh[m][c], zero-pad m >= nvalid ----
    const float* xb = x + (size_t)n * CC * TT * VV + (size_t)t0 * VV;
    for (int i = tid; i < CC * 128; i += THREADS) {
        int c = i >> 7, m = i & 127;
        float val = (m < nvalid) ? __ldg(xb + (size_t)c * (TT * VV) + m) : 0.f;
        xh[m * HS + c] = __float2half_rn(val);
    }
    if (tid < OO) {
        bqs[tid] = __ldg(bq + tid);
        bks[tid] = __ldg(bk + tid);
        bvs[tid] = __ldg(bv + tid);
    }
    for (int i = tid; i < VV * VV; i += THREADS)
        bias_s[i] = __ldg(bias_emb + __ldg(hop + i));
    __syncthreads();

    // ---- cache A-fragments of x (reused by 3 projections) ----
    u32 af[8][4];
#pragma unroll
    for (int kt = 0; kt < 8; ++kt) {
        int base = kt * 16 + q4 * 2;
        af[kt][0] = *(const u32*)(xh + (m0 + gr) * HS + base);
        af[kt][1] = *(const u32*)(xh + (m0 + gr + 8) * HS + base);
        af[kt][2] = *(const u32*)(xh + (m0 + gr) * HS + base + 8);
        af[kt][3] = *(const u32*)(xh + (m0 + gr + 8) * HS + base + 8);
    }

    float d[8][4];

    // ================= K projection =================
#pragma unroll
    for (int j = 0; j < 8; ++j) { d[j][0] = d[j][1] = d[j][2] = d[j][3] = 0.f; }
#pragma unroll
    for (int kt = 0; kt < 8; ++kt) {
#pragma unroll
        for (int j = 0; j < 8; ++j) {
            const __half* bp = kh + (co + j * 8 + gr) * HS + kt * 16 + q4 * 2;
            mma16816(d[j], af[kt][0], af[kt][1], af[kt][2], af[kt][3],
                     *(const u32*)bp, *(const u32*)(bp + 8));
        }
    }
    __syncthreads();
#pragma unroll
    for (int j = 0; j < 8; ++j) {
        int col = co + j * 8 + q4 * 2;
        float b0 = bks[col], b1 = bks[col + 1];
        *(__half2*)(kh + (m0 + gr) * HS + col) =
            __floats2half2_rn(d[j][0] + b0, d[j][1] + b1);
        *(__half2*)(kh + (m0 + gr + 8) * HS + col) =
            __floats2half2_rn(d[j][2] + b0, d[j][3] + b1);
    }

    // ================= V projection =================
#pragma unroll
    for (int j = 0; j < 8; ++j) { d[j][0] = d[j][1] = d[j][2] = d[j][3] = 0.f; }
#pragma unroll
    for (int kt = 0; kt < 8; ++kt) {
#pragma unroll
        for (int j = 0; j < 8; ++j) {
            const __half* bp = vh + (co + j * 8 + gr) * HS + kt * 16 + q4 * 2;
            mma16816(d[j], af[kt][0], af[kt][1], af[kt][2], af[kt][3],
                     *(const u32*)bp, *(const u32*)(bp + 8));
        }
    }
    __syncthreads();
    // write V'^T (+bv): vh[o][w]
#pragma unroll
    for (int j = 0; j < 8; ++j) {
        int col = co + j * 8 + q4 * 2;
        float b0 = bvs[col], b1 = bvs[col + 1];
        vh[col * HS + (m0 + gr)]           = __float2half_rn(d[j][0] + b0);
        vh[(col + 1) * HS + (m0 + gr)]     = __float2half_rn(d[j][1] + b1);
        vh[col * HS + (m0 + gr + 8)]       = __float2half_rn(d[j][2] + b0);
        vh[(col + 1) * HS + (m0 + gr + 8)] = __float2half_rn(d[j][3] + b1);
    }

    // ================= Q projection =================
#pragma unroll
    for (int j = 0; j < 8; ++j) { d[j][0] = d[j][1] = d[j][2] = d[j][3] = 0.f; }
#pragma unroll
    for (int kt = 0; kt < 8; ++kt) {
#pragma unroll
        for (int j = 0; j < 8; ++j) {
            const __half* bp = qh + (co + j * 8 + gr) * HS + kt * 16 + q4 * 2;
            mma16816(d[j], af[kt][0], af[kt][1], af[kt][2], af[kt][3],
                     *(const u32*)bp, *(const u32*)(bp + 8));
        }
    }
    __syncthreads();
#pragma unroll
    for (int j = 0; j < 8; ++j) {
        int col = co + j * 8 + q4 * 2;
        float b0 = bqs[col], b1 = bqs[col + 1];
        *(__half2*)(qh + (m0 + gr) * HS + col) =
            __floats2half2_rn(d[j][0] + b0, d[j][1] + b1);
        *(__half2*)(qh + (m0 + gr + 8) * HS + col) =
            __floats2half2_rn(d[j][2] + b0, d[j][3] + b1);
    }
    __syncthreads();   // Q', K', V'^T all ready

    // ---- per-warp block-diagonal window ----
    const int rlo = m0;
    const int rhi = min(m0 + 16, nvalid);
    const bool wact = rlo < nvalid;
    int tbmin = 0, tbmax = 0, wlo = 0, whi = 0;
    if (wact) {
        tbmin = rlo / VV;
        tbmax = (rhi - 1) / VV;
        wlo = tbmin * VV;
        whi = min(tbmax * VV + VV, nvalid);
    }

    // ================= S = Q' K'^T (windowed n-tiles) =================
#pragma unroll
    for (int j = 0; j < 8; ++j) { d[j][0] = d[j][1] = d[j][2] = d[j][3] = 0.f; }
    if (wact) {
        int jlo = max(0, (wlo - co) >> 3);
        int jhi = min(8, (whi - co + 7) >> 3);
        if (jlo < jhi) {
#pragma unroll
            for (int kt = 0; kt < 8; ++kt) {
                int base = kt * 16 + q4 * 2;
                u32 a0 = *(const u32*)(qh + (m0 + gr) * HS + base);
                u32 a1 = *(const u32*)(qh + (m0 + gr + 8) * HS + base);
                u32 a2 = *(const u32*)(qh + (m0 + gr) * HS + base + 8);
                u32 a3 = *(const u32*)(qh + (m0 + gr + 8) * HS + base + 8);
                for (int j = jlo; j < jhi; ++j) {
                    const __half* bp = kh + (co + j * 8 + gr) * HS + base;
                    mma16816(d[j], a0, a1, a2, a3,
                             *(const u32*)bp, *(const u32*)(bp + 8));
                }
            }
        }
    }
    __syncthreads();   // everyone done reading qh -> ps overlay legal

    // ---- scatter S (scaled + bias) into compact ps[m][26] ----
    const int mA = m0 + gr, mB = mA + 8;
    const bool actA = mA < nvalid, actB = mB < nvalid;
    const int tbA = mA / VV, vlA = mA - tbA * VV, loA = tbA * VV;
    const int tbB = mB / VV, vlB = mB - tbB * VV, loB = tbB * VV;
    if (wact) {
#pragma unroll
        for (int j = 0; j < 8; ++j) {
            int w = co + j * 8 + q4 * 2;
            int rA = w - loA, rB = w - loB;
            if (actA && rA >= 0 && rA < VV)
                ps[mA * 26 + rA] = fmaf(d[j][0], SCALE, bias_s[vlA * VV + rA]);
            if (actA && rA + 1 >= 0 && rA + 1 < VV)
                ps[mA * 26 + rA + 1] = fmaf(d[j][1], SCALE, bias_s[vlA * VV + rA + 1]);
            if (actB && rB >= 0 && rB < VV)
                ps[mB * 26 + rB] = fmaf(d[j][2], SCALE, bias_s[vlB * VV + rB]);
            if (actB && rB + 1 >= 0 && rB + 1 < VV)
                ps[mB * 26 + rB + 1] = fmaf(d[j][3], SCALE, bias_s[vlB * VV + rB + 1]);
        }
    }
    __syncthreads();

    // ================= softmax (thread per row) =================
    if (tid < 128 && tid < nvalid) {
        float* row = ps + tid * 26;
        float mx = row[0];
#pragma unroll
        for (int w = 1; w < VV; ++w) mx = fmaxf(mx, row[w]);
        float sum = 0.f;
        float e[VV];
#pragma unroll
        for (int w = 0; w < VV; ++w) { e[w] = __expf(row[w] - mx); sum += e[w]; }
        float inv = 1.f / sum;
#pragma unroll
        for (int w = 0; w < VV; ++w) row[w] = e[w] * inv;
    }
    __syncthreads();

    // ================= AV = P V' (windowed k-steps) =================
#pragma unroll
    for (int j = 0; j < 8; ++j) { d[j][0] = d[j][1] = d[j][2] = d[j][3] = 0.f; }
    if (wact) {
        int ktlo = wlo >> 4;
        int kthi = (whi + 15) >> 4;
        for (int kt = ktlo; kt < kthi; ++kt) {
            int k0 = kt * 16 + q4 * 2;
            // P values with rel-window mapping (0 outside the row's block)
            int rA0 = k0 - loA, rB0 = k0 - loB;
            float pA0 = (actA && rA0 >= 0 && rA0 < VV) ? ps[mA * 26 + rA0] : 0.f;
            float pA1 = (actA && rA0 + 1 >= 0 && rA0 + 1 < VV) ? ps[mA * 26 + rA0 + 1] : 0.f;
            float pB0 = (actB && rB0 >= 0 && rB0 < VV) ? ps[mB * 26 + rB0] : 0.f;
            float pB1 = (actB && rB0 + 1 >= 0 && rB0 + 1 < VV) ? ps[mB * 26 + rB0 + 1] : 0.f;
            int rA8 = rA0 + 8, rB8 = rB0 + 8;
            float pA8 = (actA && rA8 >= 0 && rA8 < VV) ? ps[mA * 26 + rA8] : 0.f;
            float pA9 = (actA && rA8 + 1 >= 0 && rA8 + 1 < VV) ? ps[mA * 26 + rA8 + 1] : 0.f;
            float pB8 = (actB && rB8 >= 0 && rB8 < VV) ? ps[mB * 26 + rB8] : 0.f;
            float pB9 = (actB && rB8 + 1 >= 0 && rB8 + 1 < VV) ? ps[mB * 26 + rB8 + 1] : 0.f;
            u32 a0 = h2u(__floats2half2_rn(pA0, pA1));
            u32 a1 = h2u(__floats2half2_rn(pB0, pB1));
            u32 a2 = h2u(__floats2half2_rn(pA8, pA9));
            u32 a3 = h2u(__floats2half2_rn(pB8, pB9));
#pragma unroll
            for (int j = 0; j < 8; ++j) {
                const __half* bp = vh + (co + j * 8 + gr) * HS + kt * 16 + q4 * 2;
                mma16816(d[j], a0, a1, a2, a3,
                         *(const u32*)bp, *(const u32*)(bp + 8));
            }
        }
    }

    // ---- write outs[m][o] (overlay on xh/kh, both dead) ----
#pragma unroll
    for (int j = 0; j < 8; ++j) {
        int col = co + j * 8 + q4 * 2;
        outs[mA * 129 + col]     = d[j][0];
        outs[mA * 129 + col + 1] = d[j][1];
        outs[mB * 129 + col]     = d[j][2];
        outs[mB * 129 + col + 1] = d[j][3];
    }
    __syncthreads();

    // ---- coalesced store: warp per o-row ----
    float* ob = out + (size_t)n * OO * TT * VV + (size_t)t0 * VV;
    for (int orow = wid; orow < OO; orow += 16) {
        float* dst = ob + (size_t)orow * (TT * VV);
#pragma unroll
        for (int p = 0; p < 4; ++p) {
            int m = lid + p * 32;
            if (m < nvalid) dst[m] = outs[m * 129 + orow];
        }
    }
}

extern "C" void kernel_launch(void* const* d_in, const int* in_sizes, int n_in,
                              void* d_out, int out_size)
{
    const float* x   = (const float*)d_in[0];
    const float* wq  = (const float*)d_in[1];
    const float* bq  = (const float*)d_in[2];
    const float* wk  = (const float*)d_in[3];
    const float* bk  = (const float*)d_in[4];
    const float* wv  = (const float*)d_in[5];
    const float* bv  = (const float*)d_in[6];
    const float* be  = (const float*)d_in[7];
    const int*   hop = (const int*)d_in[8];
    float* out = (float*)d_out;

    cudaFuncSetAttribute(phys_attn_mma,
                         cudaFuncAttributeMaxDynamicSharedMemorySize, SMEM_BYTES);

    phys_attn_mma<<<NN * TILES, THREADS, SMEM_BYTES>>>(
        x, wq, bq, wk, bk, wv, bv, be, hop, out);
}